// round 12
// baseline (speedup 1.0000x reference)
#include <cuda_runtime.h>
#include <cuda_bf16.h>
#include <cstdint>
#include <cstddef>

// Problem constants
#define SEQ   2048
#define BATCH 2
#define TOK   (SEQ * BATCH)   // 4096
#define DM    2048
#define NH    32
#define NKV   8
#define HD    64
#define KVD   (NKV * HD)      // 512

// ------------------------------------------------------------------
// Scratch (device globals; no cudaMalloc allowed)
// ------------------------------------------------------------------
__device__ float g_q[(size_t)TOK * DM];
__device__ float g_k[(size_t)TOK * KVD];
__device__ float g_v[(size_t)TOK * KVD];
__device__ float g_attn[(size_t)TOK * DM];

// Exact fp32 rounding of 10000^(-i/32), i = 0..31
__device__ __constant__ float c_invfreq[32] = {
    1.0f, 0.7498942093324559f, 0.5623413251903491f, 0.4216965034285822f,
    0.31622776601683794f, 0.23713737056616552f, 0.17782794100389228f, 0.1333521432163324f,
    0.1f, 0.07498942093324559f, 0.05623413251903491f, 0.04216965034285822f,
    0.031622776601683794f, 0.023713737056616552f, 0.017782794100389228f, 0.01333521432163324f,
    0.01f, 0.007498942093324559f, 0.005623413251903491f, 0.004216965034285822f,
    0.0031622776601683794f, 0.0023713737056616552f, 0.0017782794100389228f, 0.001333521432163324f,
    0.001f, 0.0007498942093324559f, 0.0005623413251903491f, 0.0004216965034285822f,
    0.00031622776601683794f, 0.00023713737056616552f, 0.00017782794100389228f, 0.0001333521432163324f
};

// ------------------------------------------------------------------
// tf32 helpers (baseline PTX, works on compute_103 virtual arch)
// ------------------------------------------------------------------
__device__ __forceinline__ uint32_t f2tf32(float x) {
    uint32_t r;
    asm("cvt.rna.tf32.f32 %0, %1;" : "=r"(r) : "f"(x));
    return r;
}
__device__ __forceinline__ float ex2f(float x) {
    float r;
    asm("ex2.approx.f32 %0, %1;" : "=f"(r) : "f"(x));
    return r;
}
__device__ __forceinline__ void mma_tf32(float c[4], const uint32_t a[4], const uint32_t b[2]) {
    asm volatile("mma.sync.aligned.m16n8k8.row.col.f32.tf32.tf32.f32 "
                 "{%0,%1,%2,%3}, {%4,%5,%6,%7}, {%8,%9}, {%0,%1,%2,%3};"
                 : "+f"(c[0]), "+f"(c[1]), "+f"(c[2]), "+f"(c[3])
                 : "r"(a[0]), "r"(a[1]), "r"(a[2]), "r"(a[3]), "r"(b[0]), "r"(b[1]));
}

// ==================================================================
// tf32 mma.sync GEMM core — EXACT round-6 configuration (best measured):
// CTA tile 256x128, K-chunk 32, 512 threads = 16 warps (4m x 4n),
// warp tile 64x32, LDG register prefetch + cvt-on-store, double buffer.
// A smem: [256][36] pad, B smem: [32][136] pad.
// ==================================================================
#define GBM 256
#define GBN 128
#define GBK 32
#define AS_U32 (256 * 36)   // 9216
#define BS_U32 (32 * 136)   // 4352
#define GEMM_SMEM_BYTES ((AS_U32 + BS_U32) * 2 * 4)  // 108544

template <int ROPE_MODE>
__device__ __forceinline__ void gemm_core(
    const float* __restrict__ A, const float* __restrict__ B,
    float* __restrict__ C, int N, int K, int m0, int n0,
    const int* __restrict__ pos, uint32_t* smu)
{
    uint32_t* As = smu;
    uint32_t* Bs = smu + 2 * AS_U32;

    const int tid = threadIdx.x;
    const int wid = tid >> 5, lane = tid & 31;
    const int g = lane >> 2, q = lane & 3;
    const int warp_m = wid >> 2;           // 0..3 (64 rows)
    const int warp_n = wid & 3;            // 0..3 (32 cols)

    const int arow = tid >> 3;
    const int acol4 = (tid & 7) * 4;
    const int brow = tid >> 5;
    const int bcol4 = (tid & 31) * 4;
    const float* Ag = A + (size_t)(m0 + arow) * K + acol4;
    const float* Bg = B + (size_t)brow * N + n0 + bcol4;

    float acc[4][4][4];
#pragma unroll
    for (int mt = 0; mt < 4; mt++)
#pragma unroll
        for (int nt = 0; nt < 4; nt++)
#pragma unroll
            for (int e = 0; e < 4; e++) acc[mt][nt][e] = 0.0f;

    float4 pa[4], pb[2];
#pragma unroll
    for (int it = 0; it < 4; it++)
        pa[it] = *(const float4*)(Ag + (size_t)it * 64 * K);
#pragma unroll
    for (int it = 0; it < 2; it++)
        pb[it] = *(const float4*)(Bg + (size_t)it * 16 * N);

#pragma unroll
    for (int it = 0; it < 4; it++) {
        uint32_t* ap = As + (arow + it * 64) * 36 + acol4;
        ap[0] = f2tf32(pa[it].x); ap[1] = f2tf32(pa[it].y);
        ap[2] = f2tf32(pa[it].z); ap[3] = f2tf32(pa[it].w);
    }
#pragma unroll
    for (int it = 0; it < 2; it++) {
        uint32_t* bp = Bs + (brow + it * 16) * 136 + bcol4;
        bp[0] = f2tf32(pb[it].x); bp[1] = f2tf32(pb[it].y);
        bp[2] = f2tf32(pb[it].z); bp[3] = f2tf32(pb[it].w);
    }
    __syncthreads();

    const int nCh = K / GBK;
    for (int c = 0; c < nCh; c++) {
        const int b = c & 1;
        const uint32_t* as = As + b * AS_U32;
        const uint32_t* bs = Bs + b * BS_U32;

        if (c + 1 < nCh) {
            const int k0 = (c + 1) * GBK;
#pragma unroll
            for (int it = 0; it < 4; it++)
                pa[it] = *(const float4*)(Ag + k0 + (size_t)it * 64 * K);
#pragma unroll
            for (int it = 0; it < 2; it++)
                pb[it] = *(const float4*)(Bg + (size_t)(k0 + it * 16) * N);
        }

#pragma unroll
        for (int ks = 0; ks < 4; ks++) {
            uint32_t af[4][4], bf[4][2];
            const int kc = ks * 8 + q;
#pragma unroll
            for (int mt = 0; mt < 4; mt++) {
                const int r0 = warp_m * 64 + mt * 16 + g;
                af[mt][0] = as[r0 * 36 + kc];
                af[mt][1] = as[(r0 + 8) * 36 + kc];
                af[mt][2] = as[r0 * 36 + kc + 4];
                af[mt][3] = as[(r0 + 8) * 36 + kc + 4];
            }
#pragma unroll
            for (int nt = 0; nt < 4; nt++) {
                const int n = warp_n * 32 + nt * 8 + g;
                bf[nt][0] = bs[kc * 136 + n];
                bf[nt][1] = bs[(kc + 4) * 136 + n];
            }
#pragma unroll
            for (int mt = 0; mt < 4; mt++)
#pragma unroll
                for (int nt = 0; nt < 4; nt++)
                    mma_tf32(acc[mt][nt], af[mt], bf[nt]);
        }

        if (c + 1 < nCh) {
            uint32_t* aw = As + (1 - b) * AS_U32;
            uint32_t* bw = Bs + (1 - b) * BS_U32;
#pragma unroll
            for (int it = 0; it < 4; it++) {
                uint32_t* ap = aw + (arow + it * 64) * 36 + acol4;
                ap[0] = f2tf32(pa[it].x); ap[1] = f2tf32(pa[it].y);
                ap[2] = f2tf32(pa[it].z); ap[3] = f2tf32(pa[it].w);
            }
#pragma unroll
            for (int it = 0; it < 2; it++) {
                uint32_t* bp = bw + (brow + it * 16) * 136 + bcol4;
                bp[0] = f2tf32(pb[it].x); bp[1] = f2tf32(pb[it].y);
                bp[2] = f2tf32(pb[it].z); bp[3] = f2tf32(pb[it].w);
            }
        }
        __syncthreads();
    }

    // epilogue: thread owns pairs (col, col+1) at rows (row, row+8)
#pragma unroll
    for (int mt = 0; mt < 4; mt++) {
        const int row = m0 + warp_m * 64 + mt * 16 + g;
        float p0 = 0.0f, p1 = 0.0f;
        if (ROPE_MODE) {
            p0 = (float)pos[row];
            p1 = (float)pos[row + 8];
        }
#pragma unroll
        for (int nt = 0; nt < 4; nt++) {
            const int col = n0 + warp_n * 32 + nt * 8 + q * 2;
            float v00 = acc[mt][nt][0], v01 = acc[mt][nt][1];
            float v10 = acc[mt][nt][2], v11 = acc[mt][nt][3];
            if (ROPE_MODE) {
                const int i = (col & 63) >> 1;   // RoPE pair index within head
                const float f = c_invfreq[i];
                float s0, c0, s1, c1;
                sincosf(p0 * f, &s0, &c0);
                sincosf(p1 * f, &s1, &c1);
                float o00 = fmaf(v00, c0, -v01 * s0);
                float o01 = fmaf(v00, s0,  v01 * c0);
                float o10 = fmaf(v10, c1, -v11 * s1);
                float o11 = fmaf(v10, s1,  v11 * c1);
                v00 = o00; v01 = o01; v10 = o10; v11 = o11;
            }
            *(float2*)(C + (size_t)row * N + col)       = make_float2(v00, v01);
            *(float2*)(C + (size_t)(row + 8) * N + col) = make_float2(v10, v11);
        }
    }
}

// Plain GEMM (O projection)
__global__ __launch_bounds__(512, 1)
void mma_gemm(const float* __restrict__ A, const float* __restrict__ B,
              float* __restrict__ C, int N, int K)
{
    extern __shared__ uint32_t smu[];
    gemm_core<0>(A, B, C, N, K, blockIdx.y * GBM, blockIdx.x * GBN, nullptr, smu);
}

// Fused QKV projection + RoPE.
// grid.x in [0,24): 0-15 -> Q (Wq, rope), 16-19 -> K (Wk, rope), 20-23 -> V (Wv).
__global__ __launch_bounds__(512, 1)
void mma_gemm_qkv(const float* __restrict__ X,
                  const float* __restrict__ Wq, const float* __restrict__ Wk,
                  const float* __restrict__ Wv,
                  float* __restrict__ Cq, float* __restrict__ Ck, float* __restrict__ Cv,
                  const int* __restrict__ pos)
{
    extern __shared__ uint32_t smu[];
    const int bx = blockIdx.x;
    const int m0 = blockIdx.y * GBM;
    if (bx < 16) {
        gemm_core<1>(X, Wq, Cq, DM, DM, m0, bx * GBN, pos, smu);
    } else if (bx < 20) {
        gemm_core<1>(X, Wk, Ck, KVD, DM, m0, (bx - 16) * GBN, pos, smu);
    } else {
        gemm_core<0>(X, Wv, Cv, KVD, DM, m0, (bx - 20) * GBN, nullptr, smu);
    }
}

// ==================================================================
// Tensor-core flash attention (tf32 mma.sync), causal + mask, GQA.
// Round 12: same compute structure as R4-R11, plus:
//  - K and P smem use the R9-validated k-permutation [0,4,1,5,2,6,3,7]
//    within 8-groups so fragment pairs (c, c+4) are adjacent -> LDS.64.
//    Pads = 72 make LDS.64 bank-bijective (bank64 = 36g+q = 4g+q mod 32).
//  - base-2 softmax: Q prescaled by 0.125*log2(e); exp -> ex2.approx.
//  - V smem store via single STS.128.
//  - LPT block order retained.
// ==================================================================
#define FA_KS_PAD 72
#define FA_VS_PAD 72
#define FA_PS_PAD 72
#define FA2_SMEM_U32 (64 * FA_KS_PAD + 64 * FA_VS_PAD + 128 * FA_PS_PAD + 64)
#define FA2_SMEM_BYTES (FA2_SMEM_U32 * 4)   // 73984

// 0.125 * log2(e)
#define QSCALE 0.180336880111120429f

__global__ __launch_bounds__(256, 2)
void fa_mma_kernel(const float* __restrict__ Q, const float* __restrict__ K,
                   const float* __restrict__ V, const int* __restrict__ mask,
                   float* __restrict__ Oout)
{
    extern __shared__ uint32_t su[];
    uint32_t* Ks = su;                         // [64][72], k-permuted cols
    uint32_t* Vs = Ks + 64 * FA_KS_PAD;        // [64][72], plain layout
    uint32_t* Ps = Vs + 64 * FA_VS_PAD;        // [128][72], k-permuted cols
    float*    kb = (float*)(Ps + 128 * FA_PS_PAD);

    const int tid = threadIdx.x;
    const int wid = tid >> 5, lane = tid & 31;
    const int g = lane >> 2, q = lane & 3;
    // LPT: longest CTAs (highest qt) launch first
    const int qt = (gridDim.x - 1) - blockIdx.x;
    const int h = blockIdx.y, b = blockIdx.z;
    const int q0 = qt * 128;
    const int kvh = h >> 2;
    const int row0 = q0 + wid * 16 + g;

    // P-store permuted positions for this thread's columns {2q, 2q+1}
    // (formulas validated in round 9)
    const int p0i = (2 * q < 4) ? 4 * q : 4 * q - 7;
    const int p1i = (2 * q + 1 < 4) ? 4 * q + 2 : 4 * q - 5;

    uint32_t qa[8][4];
    {
        const float* Qr0 = Q + ((size_t)(b * SEQ) + row0) * DM + h * HD;
        const float* Qr1 = Qr0 + (size_t)8 * DM;
#pragma unroll
        for (int ks = 0; ks < 8; ks++) {
            qa[ks][0] = f2tf32(Qr0[ks * 8 + q] * QSCALE);
            qa[ks][1] = f2tf32(Qr1[ks * 8 + q] * QSCALE);
            qa[ks][2] = f2tf32(Qr0[ks * 8 + q + 4] * QSCALE);
            qa[ks][3] = f2tf32(Qr1[ks * 8 + q + 4] * QSCALE);
        }
    }

    float m0r = -1e30f, m1r = -1e30f;
    float l0r = 0.0f,  l1r = 0.0f;
    float oc[8][4];
#pragma unroll
    for (int nt = 0; nt < 8; nt++)
#pragma unroll
        for (int e = 0; e < 4; e++) oc[nt][e] = 0.0f;

    uint32_t* Pw = Ps + (wid * 16) * FA_PS_PAD;

    const int ktmax = 2 * qt + 1;
    for (int kt = 0; kt <= ktmax; kt++) {
        const int k0 = kt * 64;
        __syncthreads();

#pragma unroll
        for (int it = 0; it < 4; it++) {
            int idx = tid + it * 256;
            int r = idx >> 4, c4 = (idx & 15) * 4;
            const size_t grow = ((size_t)(b * SEQ) + k0 + r) * KVD + kvh * HD + c4;
            float4 kk = *(const float4*)(K + grow);
            // K store with k-perm: cols c4..c4+3 -> base + {0,2,4,6} (+1 if c4&4)
            uint32_t* kp = Ks + r * FA_KS_PAD + (c4 & 56) + ((c4 >> 2) & 1);
            kp[0] = f2tf32(kk.x); kp[2] = f2tf32(kk.y);
            kp[4] = f2tf32(kk.z); kp[6] = f2tf32(kk.w);
            float4 vv = *(const float4*)(V + grow);
            uint32_t* vp = Vs + r * FA_VS_PAD + c4;
            *(uint4*)vp = make_uint4(f2tf32(vv.x), f2tf32(vv.y),
                                     f2tf32(vv.z), f2tf32(vv.w));
        }
        if (tid < 64)
            kb[tid] = (mask[b * SEQ + k0 + tid] > 0) ? 0.0f : -1e30f;
        __syncthreads();

        float sc[8][4];
#pragma unroll
        for (int nt = 0; nt < 8; nt++)
#pragma unroll
            for (int e = 0; e < 4; e++) sc[nt][e] = 0.0f;

#pragma unroll
        for (int ks = 0; ks < 8; ks++) {
            const int kc2 = ks * 8 + 2 * q;   // permuted: (kc, kc+4) adjacent
#pragma unroll
            for (int nt = 0; nt < 8; nt++) {
                uint32_t bq[2];
                uint2 y = *(const uint2*)&Ks[(nt * 8 + g) * FA_KS_PAD + kc2];
                bq[0] = y.x; bq[1] = y.y;
                mma_tf32(sc[nt], qa[ks], bq);
            }
        }

#pragma unroll
        for (int nt = 0; nt < 8; nt++) {
            const int c0 = k0 + nt * 8 + 2 * q;
            const float kb0 = kb[nt * 8 + 2 * q];
            const float kb1 = kb[nt * 8 + 2 * q + 1];
            sc[nt][0] = (c0     <= row0    ) ? sc[nt][0] + kb0 : -1e30f;
            sc[nt][1] = (c0 + 1 <= row0    ) ? sc[nt][1] + kb1 : -1e30f;
            sc[nt][2] = (c0     <= row0 + 8) ? sc[nt][2] + kb0 : -1e30f;
            sc[nt][3] = (c0 + 1 <= row0 + 8) ? sc[nt][3] + kb1 : -1e30f;
        }

        float mx0 = -1e30f, mx1 = -1e30f;
#pragma unroll
        for (int nt = 0; nt < 8; nt++) {
            mx0 = fmaxf(mx0, fmaxf(sc[nt][0], sc[nt][1]));
            mx1 = fmaxf(mx1, fmaxf(sc[nt][2], sc[nt][3]));
        }
        mx0 = fmaxf(mx0, __shfl_xor_sync(0xffffffffu, mx0, 1));
        mx0 = fmaxf(mx0, __shfl_xor_sync(0xffffffffu, mx0, 2));
        mx1 = fmaxf(mx1, __shfl_xor_sync(0xffffffffu, mx1, 1));
        mx1 = fmaxf(mx1, __shfl_xor_sync(0xffffffffu, mx1, 2));

        const float mn0 = fmaxf(m0r, mx0);
        const float mn1 = fmaxf(m1r, mx1);
        const float al0 = ex2f(m0r - mn0);   // base-2 domain
        const float al1 = ex2f(m1r - mn1);
        m0r = mn0; m1r = mn1;

        float s0 = 0.0f, s1 = 0.0f;
#pragma unroll
        for (int nt = 0; nt < 8; nt++) {
            float p0 = ex2f(sc[nt][0] - mn0);
            float p1 = ex2f(sc[nt][1] - mn0);
            float p2 = ex2f(sc[nt][2] - mn1);
            float p3 = ex2f(sc[nt][3] - mn1);
            s0 += p0 + p1; s1 += p2 + p3;
            const int base = nt * 8;
            Pw[g * FA_PS_PAD + base + p0i]       = f2tf32(p0);
            Pw[g * FA_PS_PAD + base + p1i]       = f2tf32(p1);
            Pw[(g + 8) * FA_PS_PAD + base + p0i] = f2tf32(p2);
            Pw[(g + 8) * FA_PS_PAD + base + p1i] = f2tf32(p3);
        }
        s0 += __shfl_xor_sync(0xffffffffu, s0, 1);
        s0 += __shfl_xor_sync(0xffffffffu, s0, 2);
        s1 += __shfl_xor_sync(0xffffffffu, s1, 1);
        s1 += __shfl_xor_sync(0xffffffffu, s1, 2);
        l0r = al0 * l0r + s0;
        l1r = al1 * l1r + s1;

#pragma unroll
        for (int nt = 0; nt < 8; nt++) {
            oc[nt][0] *= al0; oc[nt][1] *= al0;
            oc[nt][2] *= al1; oc[nt][3] *= al1;
        }
        __syncwarp();

#pragma unroll
        for (int ks = 0; ks < 8; ks++) {
            const int kc = ks * 8 + q;        // original col (for V rows)
            const int kc2 = ks * 8 + 2 * q;   // permuted col (for P loads)
            uint32_t pa[4];
            uint2 a0 = *(const uint2*)&Pw[g * FA_PS_PAD + kc2];
            uint2 a1 = *(const uint2*)&Pw[(g + 8) * FA_PS_PAD + kc2];
            pa[0] = a0.x; pa[2] = a0.y;
            pa[1] = a1.x; pa[3] = a1.y;
#pragma unroll
            for (int nt = 0; nt < 8; nt++) {
                uint32_t bv[2];
                bv[0] = Vs[kc * FA_VS_PAD + nt * 8 + g];
                bv[1] = Vs[(kc + 4) * FA_VS_PAD + nt * 8 + g];
                mma_tf32(oc[nt], pa, bv);
            }
        }
    }

    const float inv0 = 1.0f / l0r;
    const float inv1 = 1.0f / l1r;
    float* O0 = Oout + ((size_t)(b * SEQ) + row0) * DM + h * HD;
    float* O1 = O0 + (size_t)8 * DM;
#pragma unroll
    for (int nt = 0; nt < 8; nt++) {
        const int col = nt * 8 + 2 * q;
        *(float2*)(O0 + col) = make_float2(oc[nt][0] * inv0, oc[nt][1] * inv0);
        *(float2*)(O1 + col) = make_float2(oc[nt][2] * inv1, oc[nt][3] * inv1);
    }
}

// ------------------------------------------------------------------
// Launch
// ------------------------------------------------------------------
extern "C" void kernel_launch(void* const* d_in, const int* in_sizes, int n_in,
                              void* d_out, int out_size)
{
    (void)in_sizes; (void)n_in; (void)out_size;
    const float* X    = (const float*)d_in[0];
    const int*   mask = (const int*)  d_in[1];
    const int*   pos  = (const int*)  d_in[2];
    const float* Wq   = (const float*)d_in[3];
    const float* Wk   = (const float*)d_in[4];
    const float* Wv   = (const float*)d_in[5];
    const float* Wo   = (const float*)d_in[6];
    float* out = (float*)d_out;

    float *q, *k, *v, *attn;
    cudaGetSymbolAddress((void**)&q,    g_q);
    cudaGetSymbolAddress((void**)&k,    g_k);
    cudaGetSymbolAddress((void**)&v,    g_v);
    cudaGetSymbolAddress((void**)&attn, g_attn);

    cudaFuncSetAttribute(mma_gemm, cudaFuncAttributeMaxDynamicSharedMemorySize, GEMM_SMEM_BYTES);
    cudaFuncSetAttribute(mma_gemm_qkv, cudaFuncAttributeMaxDynamicSharedMemorySize, GEMM_SMEM_BYTES);
    cudaFuncSetAttribute(fa_mma_kernel, cudaFuncAttributeMaxDynamicSharedMemorySize, FA2_SMEM_BYTES);

    // Fused QKV projections + RoPE (24 column tiles: 16 Q, 4 K, 4 V)
    mma_gemm_qkv<<<dim3(24, TOK / GBM), 512, GEMM_SMEM_BYTES>>>(X, Wq, Wk, Wv, q, k, v, pos);

    // Tensor-core flash attention (k-permuted smem + base-2 softmax + LPT)
    fa_mma_kernel<<<dim3(SEQ / 128, NH, BATCH), 256, FA2_SMEM_BYTES>>>(q, k, v, mask, attn);

    // Output projection
    mma_gemm<<<dim3(DM / GBN, TOK / GBM), 512, GEMM_SMEM_BYTES>>>(attn, Wo, out, DM, DM);
}

// round 13
// speedup vs baseline: 1.5819x; 1.5819x over previous
#include <cuda_runtime.h>
#include <cuda_fp16.h>
#include <cstdint>
#include <cstddef>

// Problem constants
#define SEQ   2048
#define BATCH 2
#define TOK   (SEQ * BATCH)   // 4096
#define DM    2048
#define NH    32
#define NKV   8
#define HD    64
#define KVD   (NKV * HD)      // 512

// ------------------------------------------------------------------
// Scratch (device globals; no cudaMalloc allowed)
// ------------------------------------------------------------------
__device__ float g_q[(size_t)TOK * DM];
__device__ float g_k[(size_t)TOK * KVD];
__device__ float g_v[(size_t)TOK * KVD];
__device__ float g_attn[(size_t)TOK * DM];

// Exact fp32 rounding of 10000^(-i/32), i = 0..31
__device__ __constant__ float c_invfreq[32] = {
    1.0f, 0.7498942093324559f, 0.5623413251903491f, 0.4216965034285822f,
    0.31622776601683794f, 0.23713737056616552f, 0.17782794100389228f, 0.1333521432163324f,
    0.1f, 0.07498942093324559f, 0.05623413251903491f, 0.04216965034285822f,
    0.031622776601683794f, 0.023713737056616552f, 0.017782794100389228f, 0.01333521432163324f,
    0.01f, 0.007498942093324559f, 0.005623413251903491f, 0.004216965034285822f,
    0.0031622776601683794f, 0.0023713737056616552f, 0.0017782794100389228f, 0.001333521432163324f,
    0.001f, 0.0007498942093324559f, 0.0005623413251903491f, 0.0004216965034285822f,
    0.00031622776601683794f, 0.00023713737056616552f, 0.00017782794100389228f, 0.0001333521432163324f
};

// ------------------------------------------------------------------
// fp16 helpers (baseline PTX, works on compute_103 virtual arch)
// ------------------------------------------------------------------
__device__ __forceinline__ uint32_t pack_h2(float lo, float hi) {
    __half2 h = __floats2half2_rn(lo, hi);
    return *reinterpret_cast<uint32_t*>(&h);
}
__device__ __forceinline__ float ex2f(float x) {
    float r;
    asm("ex2.approx.f32 %0, %1;" : "=f"(r) : "f"(x));
    return r;
}
__device__ __forceinline__ void mma_f16(float c[4], const uint32_t a[4], const uint32_t b[2]) {
    asm volatile("mma.sync.aligned.m16n8k16.row.col.f32.f16.f16.f32 "
                 "{%0,%1,%2,%3}, {%4,%5,%6,%7}, {%8,%9}, {%0,%1,%2,%3};"
                 : "+f"(c[0]), "+f"(c[1]), "+f"(c[2]), "+f"(c[3])
                 : "r"(a[0]), "r"(a[1]), "r"(a[2]), "r"(a[3]), "r"(b[0]), "r"(b[1]));
}

// Weight scale 2^6 (exact) to avoid fp16 subnormals; descale in epilogue.
#define WSCALE 64.0f
#define WDESC  0.015625f

// ==================================================================
// fp16 mma.sync GEMM core (R6 shape, fp16 data):
// CTA tile 256x128, K-chunk 32, 512 threads = 16 warps (4m x 4n),
// warp tile 64x32, LDG register prefetch + cvt-on-store, double buffer.
// A smem: [256][20] f16x2 words (16 data + 4 pad; bank = 20g+q bijective)
// B smem packed k-pairs: [16][136] words (word j,n = (B[2j][n],B[2j+1][n]))
// ==================================================================
#define GBM 256
#define GBN 128
#define GBK 32
#define AS_U32 (256 * 20)   // 5120 words
#define BS_U32 (16 * 136)   // 2176 words
#define GEMM_SMEM_BYTES ((AS_U32 + BS_U32) * 2 * 4)  // 58368

template <int ROPE_MODE>
__device__ __forceinline__ void gemm_core(
    const float* __restrict__ A, const float* __restrict__ B,
    float* __restrict__ C, int N, int K, int m0, int n0,
    const int* __restrict__ pos, uint32_t* smu)
{
    uint32_t* As = smu;                 // 2 buffers
    uint32_t* Bs = smu + 2 * AS_U32;

    const int tid = threadIdx.x;
    const int wid = tid >> 5, lane = tid & 31;
    const int g = lane >> 2, q = lane & 3;
    const int warp_m = wid >> 2;           // 0..3 (64 rows)
    const int warp_n = wid & 3;            // 0..3 (32 cols)

    // loaders: A 256x32 (4 float4/thread), B 32x128 as 16 k-pairs (2 float4/thread)
    const int arow = tid >> 3;             // 0..63
    const int acol4 = (tid & 7) * 4;
    const int aw0 = (tid & 7) * 2;         // word offset in A row
    const int bj = tid >> 5;               // 0..15 (k-pair index)
    const int bcol4 = (tid & 31) * 4;
    const float* Ag = A + (size_t)(m0 + arow) * K + acol4;
    const float* Bg = B + (size_t)(2 * bj) * N + n0 + bcol4;

    float acc[4][4][4];
#pragma unroll
    for (int mt = 0; mt < 4; mt++)
#pragma unroll
        for (int nt = 0; nt < 4; nt++)
#pragma unroll
            for (int e = 0; e < 4; e++) acc[mt][nt][e] = 0.0f;

    float4 pa[4], pb0, pb1;
#pragma unroll
    for (int it = 0; it < 4; it++)
        pa[it] = *(const float4*)(Ag + (size_t)it * 64 * K);
    pb0 = *(const float4*)(Bg);
    pb1 = *(const float4*)(Bg + N);

#pragma unroll
    for (int it = 0; it < 4; it++) {
        uint2 w;
        w.x = pack_h2(pa[it].x, pa[it].y);
        w.y = pack_h2(pa[it].z, pa[it].w);
        *(uint2*)&As[(arow + it * 64) * 20 + aw0] = w;
    }
    {
        uint4 w;
        w.x = pack_h2(pb0.x * WSCALE, pb1.x * WSCALE);
        w.y = pack_h2(pb0.y * WSCALE, pb1.y * WSCALE);
        w.z = pack_h2(pb0.z * WSCALE, pb1.z * WSCALE);
        w.w = pack_h2(pb0.w * WSCALE, pb1.w * WSCALE);
        *(uint4*)&Bs[bj * 136 + bcol4] = w;
    }
    __syncthreads();

    const int nCh = K / GBK;
    for (int c = 0; c < nCh; c++) {
        const int b = c & 1;
        const uint32_t* as = As + b * AS_U32;
        const uint32_t* bs = Bs + b * BS_U32;

        if (c + 1 < nCh) {
            const int k0 = (c + 1) * GBK;
#pragma unroll
            for (int it = 0; it < 4; it++)
                pa[it] = *(const float4*)(Ag + k0 + (size_t)it * 64 * K);
            pb0 = *(const float4*)(Bg + (size_t)k0 * N);
            pb1 = *(const float4*)(Bg + (size_t)(k0 + 1) * N);
        }

#pragma unroll
        for (int kk = 0; kk < 2; kk++) {
            const int kw = kk * 8;
            uint32_t af[4][4], bf[4][2];
#pragma unroll
            for (int mt = 0; mt < 4; mt++) {
                const int r0 = warp_m * 64 + mt * 16 + g;
                af[mt][0] = as[r0 * 20 + kw + q];
                af[mt][1] = as[(r0 + 8) * 20 + kw + q];
                af[mt][2] = as[r0 * 20 + kw + q + 4];
                af[mt][3] = as[(r0 + 8) * 20 + kw + q + 4];
            }
#pragma unroll
            for (int nt = 0; nt < 4; nt++) {
                const int n = warp_n * 32 + nt * 8 + g;
                bf[nt][0] = bs[(kw + q) * 136 + n];
                bf[nt][1] = bs[(kw + q + 4) * 136 + n];
            }
#pragma unroll
            for (int mt = 0; mt < 4; mt++)
#pragma unroll
                for (int nt = 0; nt < 4; nt++)
                    mma_f16(acc[mt][nt], af[mt], bf[nt]);
        }

        if (c + 1 < nCh) {
            uint32_t* aw = As + (1 - b) * AS_U32;
            uint32_t* bw = Bs + (1 - b) * BS_U32;
#pragma unroll
            for (int it = 0; it < 4; it++) {
                uint2 w;
                w.x = pack_h2(pa[it].x, pa[it].y);
                w.y = pack_h2(pa[it].z, pa[it].w);
                *(uint2*)&aw[(arow + it * 64) * 20 + aw0] = w;
            }
            uint4 w;
            w.x = pack_h2(pb0.x * WSCALE, pb1.x * WSCALE);
            w.y = pack_h2(pb0.y * WSCALE, pb1.y * WSCALE);
            w.z = pack_h2(pb0.z * WSCALE, pb1.z * WSCALE);
            w.w = pack_h2(pb0.w * WSCALE, pb1.w * WSCALE);
            *(uint4*)&bw[bj * 136 + bcol4] = w;
        }
        __syncthreads();
    }

    // epilogue: descale weights (2^-6) + optional RoPE; thread owns pairs
    // (col, col+1) at rows (row, row+8)
#pragma unroll
    for (int mt = 0; mt < 4; mt++) {
        const int row = m0 + warp_m * 64 + mt * 16 + g;
        float p0 = 0.0f, p1 = 0.0f;
        if (ROPE_MODE) {
            p0 = (float)pos[row];
            p1 = (float)pos[row + 8];
        }
#pragma unroll
        for (int nt = 0; nt < 4; nt++) {
            const int col = n0 + warp_n * 32 + nt * 8 + q * 2;
            float v00 = acc[mt][nt][0] * WDESC, v01 = acc[mt][nt][1] * WDESC;
            float v10 = acc[mt][nt][2] * WDESC, v11 = acc[mt][nt][3] * WDESC;
            if (ROPE_MODE) {
                const int i = (col & 63) >> 1;   // RoPE pair index within head
                const float f = c_invfreq[i];
                float s0, c0, s1, c1;
                sincosf(p0 * f, &s0, &c0);
                sincosf(p1 * f, &s1, &c1);
                float o00 = fmaf(v00, c0, -v01 * s0);
                float o01 = fmaf(v00, s0,  v01 * c0);
                float o10 = fmaf(v10, c1, -v11 * s1);
                float o11 = fmaf(v10, s1,  v11 * c1);
                v00 = o00; v01 = o01; v10 = o10; v11 = o11;
            }
            *(float2*)(C + (size_t)row * N + col)       = make_float2(v00, v01);
            *(float2*)(C + (size_t)(row + 8) * N + col) = make_float2(v10, v11);
        }
    }
}

// Plain GEMM (O projection)
__global__ __launch_bounds__(512, 1)
void mma_gemm(const float* __restrict__ A, const float* __restrict__ B,
              float* __restrict__ C, int N, int K)
{
    extern __shared__ uint32_t smu[];
    gemm_core<0>(A, B, C, N, K, blockIdx.y * GBM, blockIdx.x * GBN, nullptr, smu);
}

// Fused QKV projection + RoPE.
// grid.x in [0,24): 0-15 -> Q (Wq, rope), 16-19 -> K (Wk, rope), 20-23 -> V (Wv).
__global__ __launch_bounds__(512, 1)
void mma_gemm_qkv(const float* __restrict__ X,
                  const float* __restrict__ Wq, const float* __restrict__ Wk,
                  const float* __restrict__ Wv,
                  float* __restrict__ Cq, float* __restrict__ Ck, float* __restrict__ Cv,
                  const int* __restrict__ pos)
{
    extern __shared__ uint32_t smu[];
    const int bx = blockIdx.x;
    const int m0 = blockIdx.y * GBM;
    if (bx < 16) {
        gemm_core<1>(X, Wq, Cq, DM, DM, m0, bx * GBN, pos, smu);
    } else if (bx < 20) {
        gemm_core<1>(X, Wk, Ck, KVD, DM, m0, (bx - 16) * GBN, pos, smu);
    } else {
        gemm_core<0>(X, Wv, Cv, KVD, DM, m0, (bx - 20) * GBN, nullptr, smu);
    }
}

// ==================================================================
// fp16 tensor-core flash attention, causal + mask, GQA.
// m16n8k16: P accumulator layout == A fragment layout -> P stays in
// registers (no P smem round trip). K smem [64][36] f16x2 words;
// V smem packed key-pairs [32][72] words. Base-2 softmax, LPT order.
// ==================================================================
#define FA_K_PAD 36
#define FA_V_PAD 72
#define FA3_SMEM_U32 (64 * FA_K_PAD + 32 * FA_V_PAD + 64)
#define FA3_SMEM_BYTES (FA3_SMEM_U32 * 4)   // 18688

// 0.125 * log2(e)
#define QSCALE 0.180336880111120429f

__global__ __launch_bounds__(256, 2)
void fa_mma_kernel(const float* __restrict__ Q, const float* __restrict__ K,
                   const float* __restrict__ V, const int* __restrict__ mask,
                   float* __restrict__ Oout)
{
    extern __shared__ uint32_t su[];
    uint32_t* Ksp = su;                       // [64][36] words
    uint32_t* Vsp = Ksp + 64 * FA_K_PAD;      // [32][72] words (key-pairs)
    float*    kb  = (float*)(Vsp + 32 * FA_V_PAD);

    const int tid = threadIdx.x;
    const int wid = tid >> 5, lane = tid & 31;
    const int g = lane >> 2, q = lane & 3;
    // LPT: longest CTAs (highest qt) launch first
    const int qt = (gridDim.x - 1) - blockIdx.x;
    const int h = blockIdx.y, b = blockIdx.z;
    const int q0 = qt * 128;
    const int kvh = h >> 2;
    const int row0 = q0 + wid * 16 + g;

    // Q fragments (fp16, prescaled by 0.125*log2e)
    uint32_t qa[4][4];
    {
        const float* Qr0 = Q + ((size_t)(b * SEQ) + row0) * DM + h * HD;
        const float* Qr1 = Qr0 + (size_t)8 * DM;
#pragma unroll
        for (int k4 = 0; k4 < 4; k4++) {
            const int k0 = k4 * 16 + 2 * q;
            float2 x0 = *(const float2*)(Qr0 + k0);
            float2 x1 = *(const float2*)(Qr1 + k0);
            float2 x2 = *(const float2*)(Qr0 + k0 + 8);
            float2 x3 = *(const float2*)(Qr1 + k0 + 8);
            qa[k4][0] = pack_h2(x0.x * QSCALE, x0.y * QSCALE);
            qa[k4][1] = pack_h2(x1.x * QSCALE, x1.y * QSCALE);
            qa[k4][2] = pack_h2(x2.x * QSCALE, x2.y * QSCALE);
            qa[k4][3] = pack_h2(x3.x * QSCALE, x3.y * QSCALE);
        }
    }

    float m0r = -1e30f, m1r = -1e30f;
    float l0r = 0.0f,  l1r = 0.0f;
    float oc[8][4];
#pragma unroll
    for (int nt = 0; nt < 8; nt++)
#pragma unroll
        for (int e = 0; e < 4; e++) oc[nt][e] = 0.0f;

    // V loader indices (packed key-pairs)
    const int vj = tid >> 3;           // 0..31
    const int vd8 = (tid & 7) * 8;     // 0..56

    const int ktmax = 2 * qt + 1;
    for (int kt = 0; kt <= ktmax; kt++) {
        const int k0 = kt * 64;
        __syncthreads();

        // K tile: 64x64 fp32 -> [64][36] f16x2 words
#pragma unroll
        for (int it = 0; it < 4; it++) {
            int idx = tid + it * 256;
            int r = idx >> 4, c4 = (idx & 15) * 4;
            float4 kk = *(const float4*)(K + ((size_t)(b * SEQ) + k0 + r) * KVD + kvh * HD + c4);
            uint2 w;
            w.x = pack_h2(kk.x, kk.y);
            w.y = pack_h2(kk.z, kk.w);
            *(uint2*)&Ksp[r * 36 + (c4 >> 1)] = w;
        }
        // V tile: pack key-pairs (V[2j][d], V[2j+1][d]) -> Vsp[j][d]
        {
            const float* v0 = V + ((size_t)(b * SEQ) + k0 + 2 * vj) * KVD + kvh * HD + vd8;
            const float* v1 = v0 + KVD;
            float4 a0 = *(const float4*)v0, a1 = *(const float4*)(v0 + 4);
            float4 b0 = *(const float4*)v1, b1 = *(const float4*)(v1 + 4);
            uint4 w0, w1;
            w0.x = pack_h2(a0.x, b0.x); w0.y = pack_h2(a0.y, b0.y);
            w0.z = pack_h2(a0.z, b0.z); w0.w = pack_h2(a0.w, b0.w);
            w1.x = pack_h2(a1.x, b1.x); w1.y = pack_h2(a1.y, b1.y);
            w1.z = pack_h2(a1.z, b1.z); w1.w = pack_h2(a1.w, b1.w);
            *(uint4*)&Vsp[vj * FA_V_PAD + vd8] = w0;
            *(uint4*)&Vsp[vj * FA_V_PAD + vd8 + 4] = w1;
        }
        if (tid < 64)
            kb[tid] = (mask[b * SEQ + k0 + tid] > 0) ? 0.0f : -1e30f;
        __syncthreads();

        // S = (Q*qscale) @ K^T   (4 ksteps of K=16)
        float sc[8][4];
#pragma unroll
        for (int nt = 0; nt < 8; nt++)
#pragma unroll
            for (int e = 0; e < 4; e++) sc[nt][e] = 0.0f;

#pragma unroll
        for (int k4 = 0; k4 < 4; k4++) {
            const int kw = k4 * 8;
#pragma unroll
            for (int nt = 0; nt < 8; nt++) {
                uint32_t bq[2];
                bq[0] = Ksp[(nt * 8 + g) * 36 + kw + q];
                bq[1] = Ksp[(nt * 8 + g) * 36 + kw + q + 4];
                mma_f16(sc[nt], qa[k4], bq);
            }
        }

        // causal + mask bias
#pragma unroll
        for (int nt = 0; nt < 8; nt++) {
            const int c0 = k0 + nt * 8 + 2 * q;
            const float kb0 = kb[nt * 8 + 2 * q];
            const float kb1 = kb[nt * 8 + 2 * q + 1];
            sc[nt][0] = (c0     <= row0    ) ? sc[nt][0] + kb0 : -1e30f;
            sc[nt][1] = (c0 + 1 <= row0    ) ? sc[nt][1] + kb1 : -1e30f;
            sc[nt][2] = (c0     <= row0 + 8) ? sc[nt][2] + kb0 : -1e30f;
            sc[nt][3] = (c0 + 1 <= row0 + 8) ? sc[nt][3] + kb1 : -1e30f;
        }

        float mx0 = -1e30f, mx1 = -1e30f;
#pragma unroll
        for (int nt = 0; nt < 8; nt++) {
            mx0 = fmaxf(mx0, fmaxf(sc[nt][0], sc[nt][1]));
            mx1 = fmaxf(mx1, fmaxf(sc[nt][2], sc[nt][3]));
        }
        mx0 = fmaxf(mx0, __shfl_xor_sync(0xffffffffu, mx0, 1));
        mx0 = fmaxf(mx0, __shfl_xor_sync(0xffffffffu, mx0, 2));
        mx1 = fmaxf(mx1, __shfl_xor_sync(0xffffffffu, mx1, 1));
        mx1 = fmaxf(mx1, __shfl_xor_sync(0xffffffffu, mx1, 2));

        const float mn0 = fmaxf(m0r, mx0);
        const float mn1 = fmaxf(m1r, mx1);
        const float al0 = ex2f(m0r - mn0);   // base-2 domain
        const float al1 = ex2f(m1r - mn1);
        m0r = mn0; m1r = mn1;

        // P = exp2(S - m), packed straight into fp16 A-fragments (registers)
        uint32_t pf[4][4];
        float s0 = 0.0f, s1 = 0.0f;
#pragma unroll
        for (int nt = 0; nt < 8; nt++) {
            float p0 = ex2f(sc[nt][0] - mn0);
            float p1 = ex2f(sc[nt][1] - mn0);
            float p2 = ex2f(sc[nt][2] - mn1);
            float p3 = ex2f(sc[nt][3] - mn1);
            s0 += p0 + p1; s1 += p2 + p3;
            const int k4 = nt >> 1;
            if (nt & 1) {
                pf[k4][2] = pack_h2(p0, p1);
                pf[k4][3] = pack_h2(p2, p3);
            } else {
                pf[k4][0] = pack_h2(p0, p1);
                pf[k4][1] = pack_h2(p2, p3);
            }
        }
        s0 += __shfl_xor_sync(0xffffffffu, s0, 1);
        s0 += __shfl_xor_sync(0xffffffffu, s0, 2);
        s1 += __shfl_xor_sync(0xffffffffu, s1, 1);
        s1 += __shfl_xor_sync(0xffffffffu, s1, 2);
        l0r = al0 * l0r + s0;
        l1r = al1 * l1r + s1;

#pragma unroll
        for (int nt = 0; nt < 8; nt++) {
            oc[nt][0] *= al0; oc[nt][1] *= al0;
            oc[nt][2] *= al1; oc[nt][3] *= al1;
        }

        // O += P @ V  (4 ksteps of K=16; A in registers)
#pragma unroll
        for (int k4 = 0; k4 < 4; k4++) {
#pragma unroll
            for (int nt = 0; nt < 8; nt++) {
                uint32_t bv[2];
                bv[0] = Vsp[(k4 * 8 + q) * FA_V_PAD + nt * 8 + g];
                bv[1] = Vsp[(k4 * 8 + q + 4) * FA_V_PAD + nt * 8 + g];
                mma_f16(oc[nt], pf[k4], bv);
            }
        }
    }

    const float inv0 = 1.0f / l0r;
    const float inv1 = 1.0f / l1r;
    float* O0 = Oout + ((size_t)(b * SEQ) + row0) * DM + h * HD;
    float* O1 = O0 + (size_t)8 * DM;
#pragma unroll
    for (int nt = 0; nt < 8; nt++) {
        const int col = nt * 8 + 2 * q;
        *(float2*)(O0 + col) = make_float2(oc[nt][0] * inv0, oc[nt][1] * inv0);
        *(float2*)(O1 + col) = make_float2(oc[nt][2] * inv1, oc[nt][3] * inv1);
    }
}

// ------------------------------------------------------------------
// Launch
// ------------------------------------------------------------------
extern "C" void kernel_launch(void* const* d_in, const int* in_sizes, int n_in,
                              void* d_out, int out_size)
{
    (void)in_sizes; (void)n_in; (void)out_size;
    const float* X    = (const float*)d_in[0];
    const int*   mask = (const int*)  d_in[1];
    const int*   pos  = (const int*)  d_in[2];
    const float* Wq   = (const float*)d_in[3];
    const float* Wk   = (const float*)d_in[4];
    const float* Wv   = (const float*)d_in[5];
    const float* Wo   = (const float*)d_in[6];
    float* out = (float*)d_out;

    float *q, *k, *v, *attn;
    cudaGetSymbolAddress((void**)&q,    g_q);
    cudaGetSymbolAddress((void**)&k,    g_k);
    cudaGetSymbolAddress((void**)&v,    g_v);
    cudaGetSymbolAddress((void**)&attn, g_attn);

    cudaFuncSetAttribute(mma_gemm, cudaFuncAttributeMaxDynamicSharedMemorySize, GEMM_SMEM_BYTES);
    cudaFuncSetAttribute(mma_gemm_qkv, cudaFuncAttributeMaxDynamicSharedMemorySize, GEMM_SMEM_BYTES);
    cudaFuncSetAttribute(fa_mma_kernel, cudaFuncAttributeMaxDynamicSharedMemorySize, FA3_SMEM_BYTES);

    // Fused QKV projections + RoPE (24 column tiles: 16 Q, 4 K, 4 V)
    mma_gemm_qkv<<<dim3(24, TOK / GBM), 512, GEMM_SMEM_BYTES>>>(X, Wq, Wk, Wv, q, k, v, pos);

    // fp16 tensor-core flash attention (P register-resident, LPT order)
    fa_mma_kernel<<<dim3(SEQ / 128, NH, BATCH), 256, FA3_SMEM_BYTES>>>(q, k, v, mask, attn);

    // Output projection
    mma_gemm<<<dim3(DM / GBN, TOK / GBM), 512, GEMM_SMEM_BYTES>>>(attn, Wo, out, DM, DM);
}